// round 11
// baseline (speedup 1.0000x reference)
#include <cuda_runtime.h>
#include <cuda_fp16.h>
#include <stdint.h>
#include <math.h>

#define BB 8
#define KK 2048
#define DD 1024
#define INNER 2048
#define MROWS (BB*KK)   // 16384
#define SCHUNK 128      // scan chunk length
#define NCHUNK (KK/SCHUNK)  // 16

// ---------------- device scratch (no allocs allowed) ------------------------
__device__ __half g_h  [(size_t)MROWS*DD];      // RMSNorm out fp16      32 MB
__device__ __half g_u  [(size_t)MROWS*INNER];   // silu(u) fp16          64 MB
__device__ __half g_z  [(size_t)MROWS*INNER];   // silu(z) fp16          64 MB
__device__ __half g_lg [(size_t)MROWS*INNER];   // dt logit fp16         64 MB
__device__ __half g_s  [(size_t)MROWS*INNER];   // scan*gate fp16        64 MB
__device__ __half g_wi [(size_t)2*INNER*DD];    // W_in fp16             16 MB
__device__ __half g_wd [(size_t)INNER*INNER];   // W_dt fp16              8 MB
__device__ __half g_wo [(size_t)DD*INNER];      // W_out fp16             4 MB
__device__ float  g_P  [(size_t)BB*NCHUNK*INNER];  // chunk decay prod    1 MB
__device__ float  g_q  [(size_t)BB*NCHUNK*INNER];  // chunk partial       1 MB
__device__ float  g_S  [(size_t)BB*NCHUNK*INNER];  // chunk start state   1 MB

// ---------------- PTX helpers ------------------------------------------------
__device__ __forceinline__ uint32_t smem_u32(const void* p) {
    uint32_t a;
    asm("{ .reg .u64 t; cvta.to.shared.u64 t, %1; cvt.u32.u64 %0, t; }"
        : "=r"(a) : "l"(p));
    return a;
}
__device__ __forceinline__ void cp_async16(uint32_t dst, const void* src) {
    asm volatile("cp.async.cg.shared.global [%0], [%1], 16;\n"
                 :: "r"(dst), "l"(src) : "memory");
}
__device__ __forceinline__ void cp_commit() {
    asm volatile("cp.async.commit_group;\n" ::: "memory");
}
template <int N>
__device__ __forceinline__ void cp_wait() {
    asm volatile("cp.async.wait_group %0;\n" :: "n"(N) : "memory");
}
__device__ __forceinline__ void ldsm4(uint32_t* r, uint32_t addr) {
    asm volatile("ldmatrix.sync.aligned.m8n8.x4.shared.b16 {%0,%1,%2,%3}, [%4];"
                 : "=r"(r[0]), "=r"(r[1]), "=r"(r[2]), "=r"(r[3]) : "r"(addr));
}
__device__ __forceinline__ void mma16816(float* c, const uint32_t* a,
                                         uint32_t b0, uint32_t b1) {
    asm volatile("mma.sync.aligned.m16n8k16.row.col.f32.f16.f16.f32 "
                 "{%0,%1,%2,%3}, {%4,%5,%6,%7}, {%8,%9}, {%0,%1,%2,%3};"
                 : "+f"(c[0]), "+f"(c[1]), "+f"(c[2]), "+f"(c[3])
                 : "r"(a[0]), "r"(a[1]), "r"(a[2]), "r"(a[3]), "r"(b0), "r"(b1));
}
__device__ __forceinline__ uint32_t pack_half2(float a, float b) {
    __half2 h = __halves2half2(__float2half_rn(a), __float2half_rn(b));
    return *(uint32_t*)&h;
}

// ---------------- fused weight conversion fp32 -> fp16 -----------------------
__global__ __launch_bounds__(256) void convert_all(
    const float* __restrict__ wi, const float* __restrict__ wd,
    const float* __restrict__ wo)
{
    const size_t n0 = (size_t)2*INNER*DD >> 2;
    const size_t n1 = (size_t)INNER*INNER >> 2;
    const size_t n2 = (size_t)DD*INNER   >> 2;
    size_t stride = (size_t)gridDim.x * blockDim.x;
    size_t t0 = (size_t)blockIdx.x * blockDim.x + threadIdx.x;
    for (size_t i = t0; i < n0; i += stride) {
        float4 v = ((const float4*)wi)[i];
        *(uint2*)(g_wi + 4*i) = make_uint2(pack_half2(v.x, v.y), pack_half2(v.z, v.w));
    }
    for (size_t i = t0; i < n1; i += stride) {
        float4 v = ((const float4*)wd)[i];
        *(uint2*)(g_wd + 4*i) = make_uint2(pack_half2(v.x, v.y), pack_half2(v.z, v.w));
    }
    for (size_t i = t0; i < n2; i += stride) {
        float4 v = ((const float4*)wo)[i];
        *(uint2*)(g_wo + 4*i) = make_uint2(pack_half2(v.x, v.y), pack_half2(v.z, v.w));
    }
}

// ---------------- RMSNorm -> fp16 --------------------------------------------
__global__ __launch_bounds__(256) void rmsnorm_kernel(
    const float* __restrict__ x, const float* __restrict__ w)
{
    int row = blockIdx.x;
    const float4* xr = (const float4*)(x + (size_t)row * DD);
    float4 v = xr[threadIdx.x];
    float ss = v.x*v.x + v.y*v.y + v.z*v.z + v.w*v.w;
    #pragma unroll
    for (int o = 16; o > 0; o >>= 1) ss += __shfl_xor_sync(0xffffffffu, ss, o);
    __shared__ float red[8];
    if ((threadIdx.x & 31) == 0) red[threadIdx.x >> 5] = ss;
    __syncthreads();
    float tot = red[0]+red[1]+red[2]+red[3]+red[4]+red[5]+red[6]+red[7];
    float inv = rsqrtf(tot * (1.0f / DD) + 1e-5f);
    float4 wv = ((const float4*)w)[threadIdx.x];
    size_t base = (size_t)row * DD + threadIdx.x * 4;
    *(uint2*)(g_h + base) = make_uint2(
        pack_half2(v.x*inv*wv.x, v.y*inv*wv.y),
        pack_half2(v.z*inv*wv.z, v.w*inv*wv.w));
}

// ---------------- mma.sync fp16 NT GEMM --------------------------------------
// C[M,N] = A[M,Kd]*B[N,Kd]^T, fp32 accumulate.
// MODE 1: A=g_h, B=g_wi : epi silu -> g_u (n<INNER) / g_z
// MODE 2: A=g_u, B=g_wd : epi (v + b_dt[n]) -> g_lg fp16 logit
// MODE 3: A=g_s, B=g_wo : epi x + v -> out
// CTA tile 128x64, BK=32; 8 warps 4(m)x2(n), warp tile 32x32.
// 4-stage cp.async; smem 60 KB/CTA -> 3 CTAs/SM (24 warps).
#define ROWB   80
#define A_SZ   (128*ROWB)        // 10240
#define B_SZ   (64*ROWB)         //  5120
#define STG_B  (A_SZ + B_SZ)     // 15360
#define NSTG   4
#define GEMM_SMEM (NSTG*STG_B)   // 61440

template <int MODE>
__global__ __launch_bounds__(256, 3) void gemm_tc(
    const float* __restrict__ extra, float* __restrict__ outp)
{
    const __half *A, *B0;
    int Kd;
    if (MODE == 1)      { A = g_h; B0 = g_wi; Kd = DD;    }
    else if (MODE == 2) { A = g_u; B0 = g_wd; Kd = INNER; }
    else                { A = g_s; B0 = g_wo; Kd = INNER; }
    const int NT = Kd / 32;

    extern __shared__ __align__(128) char sm[];
    uint32_t sbase = smem_u32(sm);
    const int tid = threadIdx.x;
    const int l   = tid & 31;
    const int wid = tid >> 5;
    const int bm  = blockIdx.y * 128;
    const int bn  = blockIdx.x * 64;
    const int warp_m = (wid >> 1) * 32;   // 4 m-warps
    const int warp_n = (wid & 1) * 32;    // 2 n-warps

    const __half* srcA = A  + (size_t)bm * Kd;
    const __half* srcB = B0 + (size_t)bn * Kd;

    auto load_stage = [&](int stg, int kc) {
        uint32_t base = sbase + stg * STG_B;
        #pragma unroll
        for (int i = 0; i < 3; i++) {
            int c = tid + i * 256;               // 0..767
            int isB = (c >= 512);
            int idx = isB ? (c - 512) : c;
            int row = idx >> 2;                  // A:0..127  B:0..63
            int seg = idx & 3;                   // 16B segments of 64B row
            uint32_t dst = base + (isB ? A_SZ : 0) + row * ROWB + seg * 16;
            const __half* sp = isB ? srcB : srcA;
            cp_async16(dst, (const char*)(sp + (size_t)row * Kd + kc) + seg * 16);
        }
    };

    float acc[2][4][4];
    #pragma unroll
    for (int mi = 0; mi < 2; mi++)
        #pragma unroll
        for (int ni = 0; ni < 4; ni++)
            #pragma unroll
            for (int c = 0; c < 4; c++) acc[mi][ni][c] = 0.0f;

    const uint32_t a_off = (warp_m + (l & 15)) * ROWB + 16 * (l >> 4);
    const uint32_t b_off = A_SZ + (warp_n + (l & 15)) * ROWB + 16 * (l >> 4);

    load_stage(0, 0);  cp_commit();
    load_stage(1, 32); cp_commit();
    load_stage(2, 64); cp_commit();

    for (int t = 0; t < NT; t++) {
        if (t == NT - 1)      cp_wait<0>();
        else if (t == NT - 2) cp_wait<1>();
        else                  cp_wait<2>();
        __syncthreads();
        if (t + 3 < NT) { load_stage((t + 3) & 3, (t + 3) * 32); cp_commit(); }

        uint32_t sb = sbase + (t & 3) * STG_B;
        #pragma unroll
        for (int k16 = 0; k16 < 2; k16++) {
            const uint32_t koff = k16 * 32;
            uint32_t ah[2][4], bh[2][4];
            ldsm4(ah[0], sb + a_off + koff);
            ldsm4(ah[1], sb + a_off + 16*ROWB + koff);
            ldsm4(bh[0], sb + b_off + koff);
            ldsm4(bh[1], sb + b_off + 16*ROWB + koff);
            #pragma unroll
            for (int mi = 0; mi < 2; mi++)
                #pragma unroll
                for (int ni = 0; ni < 4; ni++) {
                    const int g = ni >> 1, s = ni & 1;
                    mma16816(acc[mi][ni], ah[mi], bh[g][s], bh[g][s + 2]);
                }
        }
    }

    // ---------------- epilogue from registers --------------------------------
    #pragma unroll
    for (int mi = 0; mi < 2; mi++) {
        int m0 = bm + warp_m + mi * 16 + (l >> 2);
        #pragma unroll
        for (int ni = 0; ni < 4; ni++) {
            int n0 = bn + warp_n + ni * 8 + 2 * (l & 3);
            #pragma unroll
            for (int half = 0; half < 2; half++) {
                int m = m0 + half * 8;
                float v0 = acc[mi][ni][half * 2 + 0];
                float v1 = acc[mi][ni][half * 2 + 1];
                if (MODE == 1) {
                    float s0 = v0 / (1.f + expf(-v0));
                    float s1 = v1 / (1.f + expf(-v1));
                    if (bn < INNER)
                        *(uint32_t*)(g_u + (size_t)m * INNER + n0) = pack_half2(s0, s1);
                    else
                        *(uint32_t*)(g_z + (size_t)m * INNER + (n0 - INNER)) =
                            pack_half2(s0, s1);
                } else if (MODE == 2) {
                    float2 bv = *(const float2*)(extra + n0);
                    *(uint32_t*)(g_lg + (size_t)m * INNER + n0) =
                        pack_half2(v0 + bv.x, v1 + bv.y);
                } else {
                    size_t o = (size_t)m * DD + n0;
                    float2 xv = *(const float2*)(extra + o);
                    *(float2*)(outp + o) = make_float2(xv.x + v0, xv.y + v1);
                }
            }
        }
    }
}

// ---------------- chunked scan (half2-vectorized, 2 channels/thread) --------
__global__ __launch_bounds__(256) void scan_pass1()
{
    int b = blockIdx.z, c = blockIdx.y;
    int j = blockIdx.x * 256 + threadIdx.x;          // channel-pair 0..1023
    const int I2 = INNER / 2;
    size_t idx = ((size_t)b * KK + (size_t)c * SCHUNK) * I2 + j;
    const __half2* lg2 = (const __half2*)g_lg;
    const __half2* u2  = (const __half2*)g_u;
    float2 P = make_float2(1.f, 1.f), q = make_float2(0.f, 0.f);
    #pragma unroll 4
    for (int k = 0; k < SCHUNK; k++) {
        float2 lg = __half22float2(lg2[idx]);
        float2 u  = __half22float2(u2[idx]);
        float la = 1.f / (1.f + expf(-lg.x));
        float lb = 1.f / (1.f + expf(-lg.y));
        q.x = fmaf(la, q.x, (1.f - la) * u.x);
        q.y = fmaf(lb, q.y, (1.f - lb) * u.y);
        P.x *= la; P.y *= lb;
        idx += I2;
    }
    size_t o = ((size_t)b * NCHUNK + c) * I2 + j;
    ((float2*)g_P)[o] = P;
    ((float2*)g_q)[o] = q;
}

__global__ __launch_bounds__(256) void scan_combine()
{
    int b = blockIdx.y;
    int j = blockIdx.x * 256 + threadIdx.x;          // channel-pair 0..1023
    const int I2 = INNER / 2;
    float2 s = make_float2(0.f, 0.f);
    size_t o = (size_t)b * NCHUNK * I2 + j;
    #pragma unroll
    for (int c = 0; c < NCHUNK; c++) {
        ((float2*)g_S)[o] = s;
        float2 P = ((float2*)g_P)[o];
        float2 q = ((float2*)g_q)[o];
        s.x = fmaf(P.x, s.x, q.x);
        s.y = fmaf(P.y, s.y, q.y);
        o += I2;
    }
}

__global__ __launch_bounds__(256) void scan_pass2()
{
    int b = blockIdx.z, c = blockIdx.y;
    int j = blockIdx.x * 256 + threadIdx.x;
    const int I2 = INNER / 2;
    float2 s = ((float2*)g_S)[((size_t)b * NCHUNK + c) * I2 + j];
    size_t idx = ((size_t)b * KK + (size_t)c * SCHUNK) * I2 + j;
    const __half2* lg2 = (const __half2*)g_lg;
    const __half2* u2  = (const __half2*)g_u;
    const __half2* z2  = (const __half2*)g_z;
    __half2* s2 = (__half2*)g_s;
    #pragma unroll 4
    for (int k = 0; k < SCHUNK; k++) {
        float2 lg = __half22float2(lg2[idx]);
        float2 u  = __half22float2(u2[idx]);
        float2 zz = __half22float2(z2[idx]);
        float la = 1.f / (1.f + expf(-lg.x));
        float lb = 1.f / (1.f + expf(-lg.y));
        s.x = fmaf(la, s.x, (1.f - la) * u.x);
        s.y = fmaf(lb, s.y, (1.f - lb) * u.y);
        s2[idx] = __floats2half2_rn(s.x * zz.x, s.y * zz.y);
        idx += I2;
    }
}

// ---------------- launch ------------------------------------------------------
extern "C" void kernel_launch(void* const* d_in, const int* in_sizes, int n_in,
                              void* d_out, int out_size)
{
    const float* x      = (const float*)d_in[0];
    const float* w_norm = (const float*)d_in[1];
    const float* W_in   = (const float*)d_in[2];
    const float* W_dt   = (const float*)d_in[3];
    const float* b_dt   = (const float*)d_in[4];
    const float* W_out  = (const float*)d_in[5];
    float* out = (float*)d_out;

    cudaFuncSetAttribute(gemm_tc<1>, cudaFuncAttributeMaxDynamicSharedMemorySize, GEMM_SMEM);
    cudaFuncSetAttribute(gemm_tc<2>, cudaFuncAttributeMaxDynamicSharedMemorySize, GEMM_SMEM);
    cudaFuncSetAttribute(gemm_tc<3>, cudaFuncAttributeMaxDynamicSharedMemorySize, GEMM_SMEM);

    convert_all<<<512, 256>>>(W_in, W_dt, W_out);
    rmsnorm_kernel<<<MROWS, 256>>>(x, w_norm);

    gemm_tc<1><<<dim3(2*INNER/64, MROWS/128), 256, GEMM_SMEM>>>(nullptr, nullptr);
    gemm_tc<2><<<dim3(INNER/64,   MROWS/128), 256, GEMM_SMEM>>>(b_dt, nullptr);

    scan_pass1 <<<dim3(INNER/512, NCHUNK, BB), 256>>>();
    scan_combine<<<dim3(INNER/512, BB),        256>>>();
    scan_pass2 <<<dim3(INNER/512, NCHUNK, BB), 256>>>();

    gemm_tc<3><<<dim3(DD/64,      MROWS/128), 256, GEMM_SMEM>>>(x, out);
}

// round 12
// speedup vs baseline: 1.0877x; 1.0877x over previous
#include <cuda_runtime.h>
#include <cuda_fp16.h>
#include <stdint.h>
#include <math.h>

#define BB 8
#define KK 2048
#define DD 1024
#define INNER 2048
#define MROWS (BB*KK)   // 16384
#define SCHUNK 128      // scan chunk length
#define NCHUNK (KK/SCHUNK)  // 16

// ---------------- device scratch (no allocs allowed) ------------------------
__device__ __half g_h  [(size_t)MROWS*DD];      // RMSNorm out fp16      32 MB
__device__ __half g_u  [(size_t)MROWS*INNER];   // silu(u) fp16          64 MB
__device__ __half g_z  [(size_t)MROWS*INNER];   // silu(z) fp16          64 MB
__device__ __half g_lg [(size_t)MROWS*INNER];   // dt logit fp16         64 MB
__device__ __half g_s  [(size_t)MROWS*INNER];   // scan*gate fp16        64 MB
__device__ __half g_wi [(size_t)2*INNER*DD];    // W_in fp16             16 MB
__device__ __half g_wd [(size_t)INNER*INNER];   // W_dt fp16              8 MB
__device__ __half g_wo [(size_t)DD*INNER];      // W_out fp16             4 MB
__device__ float  g_P  [(size_t)BB*NCHUNK*INNER];  // chunk decay prod    1 MB
__device__ float  g_q  [(size_t)BB*NCHUNK*INNER];  // chunk partial       1 MB
__device__ float  g_S  [(size_t)BB*NCHUNK*INNER];  // chunk start state   1 MB

// ---------------- PTX helpers ------------------------------------------------
__device__ __forceinline__ uint32_t smem_u32(const void* p) {
    uint32_t a;
    asm("{ .reg .u64 t; cvta.to.shared.u64 t, %1; cvt.u32.u64 %0, t; }"
        : "=r"(a) : "l"(p));
    return a;
}
__device__ __forceinline__ void cp_async16(uint32_t dst, const void* src) {
    asm volatile("cp.async.cg.shared.global [%0], [%1], 16;\n"
                 :: "r"(dst), "l"(src) : "memory");
}
__device__ __forceinline__ void cp_commit() {
    asm volatile("cp.async.commit_group;\n" ::: "memory");
}
template <int N>
__device__ __forceinline__ void cp_wait() {
    asm volatile("cp.async.wait_group %0;\n" :: "n"(N) : "memory");
}
__device__ __forceinline__ void ldsm4(uint32_t* r, uint32_t addr) {
    asm volatile("ldmatrix.sync.aligned.m8n8.x4.shared.b16 {%0,%1,%2,%3}, [%4];"
                 : "=r"(r[0]), "=r"(r[1]), "=r"(r[2]), "=r"(r[3]) : "r"(addr));
}
__device__ __forceinline__ void mma16816(float* c, const uint32_t* a,
                                         uint32_t b0, uint32_t b1) {
    asm volatile("mma.sync.aligned.m16n8k16.row.col.f32.f16.f16.f32 "
                 "{%0,%1,%2,%3}, {%4,%5,%6,%7}, {%8,%9}, {%0,%1,%2,%3};"
                 : "+f"(c[0]), "+f"(c[1]), "+f"(c[2]), "+f"(c[3])
                 : "r"(a[0]), "r"(a[1]), "r"(a[2]), "r"(a[3]), "r"(b0), "r"(b1));
}
__device__ __forceinline__ uint32_t pack_half2(float a, float b) {
    __half2 h = __halves2half2(__float2half_rn(a), __float2half_rn(b));
    return *(uint32_t*)&h;
}

// ---------------- fused weight conversion fp32 -> fp16 -----------------------
__global__ __launch_bounds__(256) void convert_all(
    const float* __restrict__ wi, const float* __restrict__ wd,
    const float* __restrict__ wo)
{
    const size_t n0 = (size_t)2*INNER*DD >> 2;
    const size_t n1 = (size_t)INNER*INNER >> 2;
    const size_t n2 = (size_t)DD*INNER   >> 2;
    size_t stride = (size_t)gridDim.x * blockDim.x;
    size_t t0 = (size_t)blockIdx.x * blockDim.x + threadIdx.x;
    for (size_t i = t0; i < n0; i += stride) {
        float4 v = ((const float4*)wi)[i];
        *(uint2*)(g_wi + 4*i) = make_uint2(pack_half2(v.x, v.y), pack_half2(v.z, v.w));
    }
    for (size_t i = t0; i < n1; i += stride) {
        float4 v = ((const float4*)wd)[i];
        *(uint2*)(g_wd + 4*i) = make_uint2(pack_half2(v.x, v.y), pack_half2(v.z, v.w));
    }
    for (size_t i = t0; i < n2; i += stride) {
        float4 v = ((const float4*)wo)[i];
        *(uint2*)(g_wo + 4*i) = make_uint2(pack_half2(v.x, v.y), pack_half2(v.z, v.w));
    }
}

// ---------------- RMSNorm -> fp16 --------------------------------------------
__global__ __launch_bounds__(256) void rmsnorm_kernel(
    const float* __restrict__ x, const float* __restrict__ w)
{
    int row = blockIdx.x;
    const float4* xr = (const float4*)(x + (size_t)row * DD);
    float4 v = xr[threadIdx.x];
    float ss = v.x*v.x + v.y*v.y + v.z*v.z + v.w*v.w;
    #pragma unroll
    for (int o = 16; o > 0; o >>= 1) ss += __shfl_xor_sync(0xffffffffu, ss, o);
    __shared__ float red[8];
    if ((threadIdx.x & 31) == 0) red[threadIdx.x >> 5] = ss;
    __syncthreads();
    float tot = red[0]+red[1]+red[2]+red[3]+red[4]+red[5]+red[6]+red[7];
    float inv = rsqrtf(tot * (1.0f / DD) + 1e-5f);
    float4 wv = ((const float4*)w)[threadIdx.x];
    size_t base = (size_t)row * DD + threadIdx.x * 4;
    *(uint2*)(g_h + base) = make_uint2(
        pack_half2(v.x*inv*wv.x, v.y*inv*wv.y),
        pack_half2(v.z*inv*wv.z, v.w*inv*wv.w));
}

// ---------------- mma.sync fp16 NT GEMM --------------------------------------
// C[M,N] = A[M,Kd]*B[N,Kd]^T, fp32 accumulate.
// MODE 1: A=g_h, B=g_wi : epi silu -> g_u (n<INNER) / g_z
// MODE 2: A=g_u, B=g_wd : epi (v + b_dt[n]) -> g_lg fp16 logit
// MODE 3: A=g_s, B=g_wo : epi x + v -> out
// CTA = 128 threads (4 warps as 2m x 2n), warp tile 64x64, CTA tile 128x128.
// BK=64, 3-stage cp.async, 108 KB smem/CTA -> 2 CTAs/SM.
// LDSM:MMA = 8:32 per k16 (density 4.0).
#define ROWB  144
#define TEN_B (128*ROWB)        // 18432 per tensor per stage
#define NSTG  3
#define STG_B (2*TEN_B)         // 36864
#define GEMM_SMEM (NSTG*STG_B)  // 110592 -> 2 CTAs/SM

template <int MODE>
__global__ __launch_bounds__(128, 2) void gemm_tc(
    const float* __restrict__ extra, float* __restrict__ outp)
{
    const __half *A, *B0;
    int Kd;
    if (MODE == 1)      { A = g_h; B0 = g_wi; Kd = DD;    }
    else if (MODE == 2) { A = g_u; B0 = g_wd; Kd = INNER; }
    else                { A = g_s; B0 = g_wo; Kd = INNER; }
    const int NT = Kd / 64;

    extern __shared__ __align__(128) char sm[];
    uint32_t sbase = smem_u32(sm);
    const int tid = threadIdx.x;
    const int l   = tid & 31;
    const int wid = tid >> 5;            // 0..3
    const int bm  = blockIdx.y * 128;
    const int bn  = blockIdx.x * 128;
    const int warp_m = (wid >> 1) * 64;  // 2 m-warps
    const int warp_n = (wid & 1) * 64;   // 2 n-warps

    const __half* srcA = A  + (size_t)bm * Kd;
    const __half* srcB = B0 + (size_t)bn * Kd;

    auto load_stage = [&](int stg, int kc) {
        uint32_t base = sbase + stg * STG_B;
        #pragma unroll
        for (int i = 0; i < 16; i++) {
            int c   = tid + i * 128;          // 0..2047
            int tns = c >> 10;                // 0: A, 1: B
            int idx = c & 1023;
            int row = idx >> 3;               // 0..127
            int seg = idx & 7;                // 16B segments of 128B row
            uint32_t dst = base + tns * TEN_B + row * ROWB + seg * 16;
            const __half* sp = tns ? srcB : srcA;
            cp_async16(dst, (const char*)(sp + (size_t)row * Kd + kc) + seg * 16);
        }
    };

    float acc[4][8][4];
    #pragma unroll
    for (int mi = 0; mi < 4; mi++)
        #pragma unroll
        for (int ni = 0; ni < 8; ni++)
            #pragma unroll
            for (int c = 0; c < 4; c++) acc[mi][ni][c] = 0.0f;

    const uint32_t a_off = (warp_m + (l & 15)) * ROWB + 16 * (l >> 4);
    const uint32_t b_off = TEN_B + (warp_n + (l & 15)) * ROWB + 16 * (l >> 4);

    load_stage(0, 0);  cp_commit();
    load_stage(1, 64); cp_commit();

    for (int t = 0; t < NT; t++) {
        if (t + 1 < NT) cp_wait<1>();
        else            cp_wait<0>();
        __syncthreads();
        if (t + 2 < NT) { load_stage((t + 2) % 3, (t + 2) * 64); cp_commit(); }

        uint32_t sb = sbase + (t % 3) * STG_B;
        #pragma unroll
        for (int k16 = 0; k16 < 4; k16++) {
            const uint32_t koff = k16 * 32;
            uint32_t ah[4][4], bh[4][4];
            #pragma unroll
            for (int mi = 0; mi < 4; mi++)
                ldsm4(ah[mi], sb + a_off + mi * (16*ROWB) + koff);
            #pragma unroll
            for (int g = 0; g < 4; g++)
                ldsm4(bh[g], sb + b_off + g * (16*ROWB) + koff);
            #pragma unroll
            for (int mi = 0; mi < 4; mi++)
                #pragma unroll
                for (int ni = 0; ni < 8; ni++) {
                    const int g = ni >> 1, s = ni & 1;
                    mma16816(acc[mi][ni], ah[mi], bh[g][s], bh[g][s + 2]);
                }
        }
    }

    // ---------------- epilogue from registers --------------------------------
    #pragma unroll
    for (int mi = 0; mi < 4; mi++) {
        int m0 = bm + warp_m + mi * 16 + (l >> 2);
        #pragma unroll
        for (int ni = 0; ni < 8; ni++) {
            int n0 = bn + warp_n + ni * 8 + 2 * (l & 3);
            #pragma unroll
            for (int half = 0; half < 2; half++) {
                int m = m0 + half * 8;
                float v0 = acc[mi][ni][half * 2 + 0];
                float v1 = acc[mi][ni][half * 2 + 1];
                if (MODE == 1) {
                    float s0 = v0 / (1.f + expf(-v0));
                    float s1 = v1 / (1.f + expf(-v1));
                    if (bn < INNER)
                        *(uint32_t*)(g_u + (size_t)m * INNER + n0) = pack_half2(s0, s1);
                    else
                        *(uint32_t*)(g_z + (size_t)m * INNER + (n0 - INNER)) =
                            pack_half2(s0, s1);
                } else if (MODE == 2) {
                    float2 bv = *(const float2*)(extra + n0);
                    *(uint32_t*)(g_lg + (size_t)m * INNER + n0) =
                        pack_half2(v0 + bv.x, v1 + bv.y);
                } else {
                    size_t o = (size_t)m * DD + n0;
                    float2 xv = *(const float2*)(extra + o);
                    *(float2*)(outp + o) = make_float2(xv.x + v0, xv.y + v1);
                }
            }
        }
    }
}

// ---------------- chunked scan (half2-vectorized, 2 channels/thread) --------
__global__ __launch_bounds__(256) void scan_pass1()
{
    int b = blockIdx.z, c = blockIdx.y;
    int j = blockIdx.x * 256 + threadIdx.x;          // channel-pair 0..1023
    const int I2 = INNER / 2;
    size_t idx = ((size_t)b * KK + (size_t)c * SCHUNK) * I2 + j;
    const __half2* lg2 = (const __half2*)g_lg;
    const __half2* u2  = (const __half2*)g_u;
    float2 P = make_float2(1.f, 1.f), q = make_float2(0.f, 0.f);
    #pragma unroll 4
    for (int k = 0; k < SCHUNK; k++) {
        float2 lg = __half22float2(lg2[idx]);
        float2 u  = __half22float2(u2[idx]);
        float la = 1.f / (1.f + expf(-lg.x));
        float lb = 1.f / (1.f + expf(-lg.y));
        q.x = fmaf(la, q.x, (1.f - la) * u.x);
        q.y = fmaf(lb, q.y, (1.f - lb) * u.y);
        P.x *= la; P.y *= lb;
        idx += I2;
    }
    size_t o = ((size_t)b * NCHUNK + c) * I2 + j;
    ((float2*)g_P)[o] = P;
    ((float2*)g_q)[o] = q;
}

__global__ __launch_bounds__(256) void scan_combine()
{
    int b = blockIdx.y;
    int j = blockIdx.x * 256 + threadIdx.x;          // channel-pair 0..1023
    const int I2 = INNER / 2;
    float2 s = make_float2(0.f, 0.f);
    size_t o = (size_t)b * NCHUNK * I2 + j;
    #pragma unroll
    for (int c = 0; c < NCHUNK; c++) {
        ((float2*)g_S)[o] = s;
        float2 P = ((float2*)g_P)[o];
        float2 q = ((float2*)g_q)[o];
        s.x = fmaf(P.x, s.x, q.x);
        s.y = fmaf(P.y, s.y, q.y);
        o += I2;
    }
}

__global__ __launch_bounds__(256) void scan_pass2()
{
    int b = blockIdx.z, c = blockIdx.y;
    int j = blockIdx.x * 256 + threadIdx.x;
    const int I2 = INNER / 2;
    float2 s = ((float2*)g_S)[((size_t)b * NCHUNK + c) * I2 + j];
    size_t idx = ((size_t)b * KK + (size_t)c * SCHUNK) * I2 + j;
    const __half2* lg2 = (const __half2*)g_lg;
    const __half2* u2  = (const __half2*)g_u;
    const __half2* z2  = (const __half2*)g_z;
    __half2* s2 = (__half2*)g_s;
    #pragma unroll 4
    for (int k = 0; k < SCHUNK; k++) {
        float2 lg = __half22float2(lg2[idx]);
        float2 u  = __half22float2(u2[idx]);
        float2 zz = __half22float2(z2[idx]);
        float la = 1.f / (1.f + expf(-lg.x));
        float lb = 1.f / (1.f + expf(-lg.y));
        s.x = fmaf(la, s.x, (1.f - la) * u.x);
        s.y = fmaf(lb, s.y, (1.f - lb) * u.y);
        s2[idx] = __floats2half2_rn(s.x * zz.x, s.y * zz.y);
        idx += I2;
    }
}

// ---------------- launch ------------------------------------------------------
extern "C" void kernel_launch(void* const* d_in, const int* in_sizes, int n_in,
                              void* d_out, int out_size)
{
    const float* x      = (const float*)d_in[0];
    const float* w_norm = (const float*)d_in[1];
    const float* W_in   = (const float*)d_in[2];
    const float* W_dt   = (const float*)d_in[3];
    const float* b_dt   = (const float*)d_in[4];
    const float* W_out  = (const float*)d_in[5];
    float* out = (float*)d_out;

    cudaFuncSetAttribute(gemm_tc<1>, cudaFuncAttributeMaxDynamicSharedMemorySize, GEMM_SMEM);
    cudaFuncSetAttribute(gemm_tc<2>, cudaFuncAttributeMaxDynamicSharedMemorySize, GEMM_SMEM);
    cudaFuncSetAttribute(gemm_tc<3>, cudaFuncAttributeMaxDynamicSharedMemorySize, GEMM_SMEM);

    convert_all<<<512, 256>>>(W_in, W_dt, W_out);
    rmsnorm_kernel<<<MROWS, 256>>>(x, w_norm);

    gemm_tc<1><<<dim3(2*INNER/128, MROWS/128), 128, GEMM_SMEM>>>(nullptr, nullptr);
    gemm_tc<2><<<dim3(INNER/128,   MROWS/128), 128, GEMM_SMEM>>>(b_dt, nullptr);

    scan_pass1 <<<dim3(INNER/512, NCHUNK, BB), 256>>>();
    scan_combine<<<dim3(INNER/512, BB),        256>>>();
    scan_pass2 <<<dim3(INNER/512, NCHUNK, BB), 256>>>();

    gemm_tc<3><<<dim3(DD/128,      MROWS/128), 128, GEMM_SMEM>>>(x, out);
}

// round 13
// speedup vs baseline: 1.1884x; 1.0927x over previous
#include <cuda_runtime.h>
#include <cuda_fp16.h>
#include <stdint.h>
#include <math.h>

#define BB 8
#define KK 2048
#define DD 1024
#define INNER 2048
#define MROWS (BB*KK)   // 16384
#define SCHUNK 128      // scan chunk length (== GEMM tile M)
#define NCHUNK (KK/SCHUNK)  // 16

// ---------------- device scratch (no allocs allowed) ------------------------
__device__ __half g_h  [(size_t)MROWS*DD];      // RMSNorm out fp16      32 MB
__device__ __half g_u  [(size_t)MROWS*INNER];   // silu(u) fp16          64 MB
__device__ __half g_z  [(size_t)MROWS*INNER];   // silu(z) fp16          64 MB
__device__ __half g_lam[(size_t)MROWS*INNER];   // lambda fp16           64 MB
__device__ __half g_s  [(size_t)MROWS*INNER];   // scan*gate fp16        64 MB
__device__ __half g_wi [(size_t)2*INNER*DD];    // W_in fp16             16 MB
__device__ __half g_wd [(size_t)INNER*INNER];   // W_dt fp16              8 MB
__device__ __half g_wo [(size_t)DD*INNER];      // W_out fp16             4 MB
__device__ float  g_P  [(size_t)BB*NCHUNK*INNER];  // chunk decay prod    1 MB
__device__ float  g_q  [(size_t)BB*NCHUNK*INNER];  // chunk partial       1 MB

// ---------------- PTX helpers ------------------------------------------------
__device__ __forceinline__ uint32_t smem_u32(const void* p) {
    uint32_t a;
    asm("{ .reg .u64 t; cvta.to.shared.u64 t, %1; cvt.u32.u64 %0, t; }"
        : "=r"(a) : "l"(p));
    return a;
}
__device__ __forceinline__ void cp_async16(uint32_t dst, const void* src) {
    asm volatile("cp.async.cg.shared.global [%0], [%1], 16;\n"
                 :: "r"(dst), "l"(src) : "memory");
}
__device__ __forceinline__ void cp_commit() {
    asm volatile("cp.async.commit_group;\n" ::: "memory");
}
template <int N>
__device__ __forceinline__ void cp_wait() {
    asm volatile("cp.async.wait_group %0;\n" :: "n"(N) : "memory");
}
__device__ __forceinline__ void ldsm4(uint32_t* r, uint32_t addr) {
    asm volatile("ldmatrix.sync.aligned.m8n8.x4.shared.b16 {%0,%1,%2,%3}, [%4];"
                 : "=r"(r[0]), "=r"(r[1]), "=r"(r[2]), "=r"(r[3]) : "r"(addr));
}
__device__ __forceinline__ void mma16816(float* c, const uint32_t* a,
                                         uint32_t b0, uint32_t b1) {
    asm volatile("mma.sync.aligned.m16n8k16.row.col.f32.f16.f16.f32 "
                 "{%0,%1,%2,%3}, {%4,%5,%6,%7}, {%8,%9}, {%0,%1,%2,%3};"
                 : "+f"(c[0]), "+f"(c[1]), "+f"(c[2]), "+f"(c[3])
                 : "r"(a[0]), "r"(a[1]), "r"(a[2]), "r"(a[3]), "r"(b0), "r"(b1));
}
__device__ __forceinline__ uint32_t pack_half2(float a, float b) {
    __half2 h = __halves2half2(__float2half_rn(a), __float2half_rn(b));
    return *(uint32_t*)&h;
}

// ---------------- fused weight conversion fp32 -> fp16 -----------------------
__global__ __launch_bounds__(256) void convert_all(
    const float* __restrict__ wi, const float* __restrict__ wd,
    const float* __restrict__ wo)
{
    const size_t n0 = (size_t)2*INNER*DD >> 2;
    const size_t n1 = (size_t)INNER*INNER >> 2;
    const size_t n2 = (size_t)DD*INNER   >> 2;
    size_t stride = (size_t)gridDim.x * blockDim.x;
    size_t t0 = (size_t)blockIdx.x * blockDim.x + threadIdx.x;
    for (size_t i = t0; i < n0; i += stride) {
        float4 v = ((const float4*)wi)[i];
        *(uint2*)(g_wi + 4*i) = make_uint2(pack_half2(v.x, v.y), pack_half2(v.z, v.w));
    }
    for (size_t i = t0; i < n1; i += stride) {
        float4 v = ((const float4*)wd)[i];
        *(uint2*)(g_wd + 4*i) = make_uint2(pack_half2(v.x, v.y), pack_half2(v.z, v.w));
    }
    for (size_t i = t0; i < n2; i += stride) {
        float4 v = ((const float4*)wo)[i];
        *(uint2*)(g_wo + 4*i) = make_uint2(pack_half2(v.x, v.y), pack_half2(v.z, v.w));
    }
}

// ---------------- RMSNorm -> fp16 --------------------------------------------
__global__ __launch_bounds__(256) void rmsnorm_kernel(
    const float* __restrict__ x, const float* __restrict__ w)
{
    int row = blockIdx.x;
    const float4* xr = (const float4*)(x + (size_t)row * DD);
    float4 v = xr[threadIdx.x];
    float ss = v.x*v.x + v.y*v.y + v.z*v.z + v.w*v.w;
    #pragma unroll
    for (int o = 16; o > 0; o >>= 1) ss += __shfl_xor_sync(0xffffffffu, ss, o);
    __shared__ float red[8];
    if ((threadIdx.x & 31) == 0) red[threadIdx.x >> 5] = ss;
    __syncthreads();
    float tot = red[0]+red[1]+red[2]+red[3]+red[4]+red[5]+red[6]+red[7];
    float inv = rsqrtf(tot * (1.0f / DD) + 1e-5f);
    float4 wv = ((const float4*)w)[threadIdx.x];
    size_t base = (size_t)row * DD + threadIdx.x * 4;
    *(uint2*)(g_h + base) = make_uint2(
        pack_half2(v.x*inv*wv.x, v.y*inv*wv.y),
        pack_half2(v.z*inv*wv.z, v.w*inv*wv.w));
}

// ---------------- mma.sync fp16 NT GEMM (best R10 config) --------------------
// C[M,N] = A[M,Kd]*B[N,Kd]^T, fp32 accumulate.
// MODE 1: A=g_h, B=g_wi : epi silu -> g_u (n<INNER) / g_z
// MODE 2: A=g_u, B=g_wd : epi lambda=sigmoid(v+b_dt) -> g_lam
//                         + FUSED chunk-scan pass1 -> g_P, g_q
// MODE 3: A=g_s, B=g_wo : epi x + v -> out
// BM=BN=128, BK=64; 8 warps 2(m)x4(n), warp tile 64x32; 3-stage cp.async.
#define ROWB  144
#define TEN_B (128*ROWB)        // 18432 per tensor per stage
#define NSTG  3
#define STG_B (2*TEN_B)         // 36864
#define GEMM_SMEM (NSTG*STG_B)  // 110592 -> 2 CTAs/SM
#define LAM_PITCH 130           // halves; pitch/2 odd -> conflict-light

template <int MODE>
__global__ __launch_bounds__(256, 2) void gemm_tc(
    const float* __restrict__ extra, float* __restrict__ outp)
{
    const __half *A, *B0;
    int Kd;
    if (MODE == 1)      { A = g_h; B0 = g_wi; Kd = DD;    }
    else if (MODE == 2) { A = g_u; B0 = g_wd; Kd = INNER; }
    else                { A = g_s; B0 = g_wo; Kd = INNER; }
    const int NT = Kd / 64;

    extern __shared__ __align__(128) char sm[];
    uint32_t sbase = smem_u32(sm);
    const int tid = threadIdx.x;
    const int l   = tid & 31;
    const int wid = tid >> 5;
    const int bm  = blockIdx.y * 128;
    const int bn  = blockIdx.x * 128;
    const int warp_m = (wid & 1) * 64;
    const int warp_n = (wid >> 1) * 32;

    const __half* srcA = A  + (size_t)bm * Kd;
    const __half* srcB = B0 + (size_t)bn * Kd;

    auto load_stage = [&](int stg, int kc) {
        uint32_t base = sbase + stg * STG_B;
        #pragma unroll
        for (int i = 0; i < 8; i++) {
            int c   = tid + i * 256;          // 0..2047
            int tns = c >> 10;                // 0: A, 1: B
            int idx = c & 1023;
            int row = idx >> 3;               // 0..127
            int seg = idx & 7;                // 16B segments of 128B row
            uint32_t dst = base + tns * TEN_B + row * ROWB + seg * 16;
            const __half* sp = tns ? srcB : srcA;
            cp_async16(dst, (const char*)(sp + (size_t)row * Kd + kc) + seg * 16);
        }
    };

    float acc[4][4][4];
    #pragma unroll
    for (int mi = 0; mi < 4; mi++)
        #pragma unroll
        for (int ni = 0; ni < 4; ni++)
            #pragma unroll
            for (int c = 0; c < 4; c++) acc[mi][ni][c] = 0.0f;

    const uint32_t a_off = (warp_m + (l & 15)) * ROWB + 16 * (l >> 4);
    const uint32_t b_off = TEN_B + (warp_n + (l & 15)) * ROWB + 16 * (l >> 4);

    load_stage(0, 0);  cp_commit();
    load_stage(1, 64); cp_commit();

    uint32_t bh[2][2][4];   // [buf][g][frag] — B frags double-buffered over k16

    for (int t = 0; t < NT; t++) {
        if (t + 1 < NT) cp_wait<1>();
        else            cp_wait<0>();
        __syncthreads();
        if (t + 2 < NT) { load_stage((t + 2) % 3, (t + 2) * 64); cp_commit(); }

        uint32_t sb = sbase + (t % 3) * STG_B;

        #pragma unroll
        for (int g = 0; g < 2; g++)
            ldsm4(bh[0][g], sb + b_off + g * (16*ROWB));

        #pragma unroll
        for (int k16 = 0; k16 < 4; k16++) {
            const int cur = k16 & 1, nxt = cur ^ 1;
            const uint32_t koff = k16 * 32;
            if (k16 < 3) {
                #pragma unroll
                for (int g = 0; g < 2; g++)
                    ldsm4(bh[nxt][g], sb + b_off + g * (16*ROWB) + koff + 32);
            }
            #pragma unroll
            for (int mh = 0; mh < 2; mh++) {
                uint32_t ah[2][4];
                ldsm4(ah[0], sb + a_off + (mh*2+0) * (16*ROWB) + koff);
                ldsm4(ah[1], sb + a_off + (mh*2+1) * (16*ROWB) + koff);
                #pragma unroll
                for (int mi2 = 0; mi2 < 2; mi2++) {
                    const int mi = mh * 2 + mi2;
                    #pragma unroll
                    for (int ni = 0; ni < 4; ni++) {
                        const int g = ni >> 1, s = ni & 1;
                        mma16816(acc[mi][ni], ah[mi2],
                                 bh[cur][g][s], bh[cur][g][s + 2]);
                    }
                }
            }
        }
    }

    // ---------------- epilogue ----------------------------------------------
    if (MODE == 2) {
        // lambda -> g_lam and stage-smem (reused); then fused chunk-scan pass1
        __syncthreads();                     // all stage-smem reads done
        __half* lam_sm = (__half*)sm;
        #pragma unroll
        for (int mi = 0; mi < 4; mi++) {
            int mloc0 = warp_m + mi * 16 + (l >> 2);
            #pragma unroll
            for (int ni = 0; ni < 4; ni++) {
                int nloc = warp_n + ni * 8 + 2 * (l & 3);
                float2 bv = *(const float2*)(extra + bn + nloc);
                #pragma unroll
                for (int half = 0; half < 2; half++) {
                    int mloc = mloc0 + half * 8;
                    float l0 = 1.f / (1.f + expf(-(acc[mi][ni][half*2+0] + bv.x)));
                    float l1 = 1.f / (1.f + expf(-(acc[mi][ni][half*2+1] + bv.y)));
                    uint32_t p = pack_half2(l0, l1);
                    *(uint32_t*)(g_lam + (size_t)(bm + mloc) * INNER + bn + nloc) = p;
                    *(uint32_t*)(lam_sm + mloc * LAM_PITCH + nloc) = p;
                }
            }
        }
        __syncthreads();
        // per-channel half-chunk recurrence: 2 halves of 64 rows
        int j  = tid & 127;
        int hh = tid >> 7;
        const __half* urow = g_u + (size_t)(bm + hh * 64) * INNER + bn + j;
        float P = 1.f, q = 0.f;
        #pragma unroll 8
        for (int r = 0; r < 64; r++) {
            float lam = __half2float(lam_sm[(hh * 64 + r) * LAM_PITCH + j]);
            float uu  = __half2float(urow[(size_t)r * INNER]);
            q = fmaf(lam, q, (1.f - lam) * uu);
            P *= lam;
        }
        float* Psm = (float*)(sm + 34048);   // past lam region (128*130*2=33280)
        float* Qsm = Psm + 256;
        Psm[tid] = P; Qsm[tid] = q;
        __syncthreads();
        if (tid < 128) {
            float P0 = Psm[tid],       q0 = Qsm[tid];
            float P1 = Psm[tid + 128], q1 = Qsm[tid + 128];
            int b = bm >> 11;                 // / KK
            int c = (bm & (KK - 1)) >> 7;     // / SCHUNK
            size_t o = ((size_t)b * NCHUNK + c) * INNER + bn + j;
            g_P[o] = P0 * P1;
            g_q[o] = fmaf(P1, q0, q1);
        }
        return;
    }

    #pragma unroll
    for (int mi = 0; mi < 4; mi++) {
        int m0 = bm + warp_m + mi * 16 + (l >> 2);
        #pragma unroll
        for (int ni = 0; ni < 4; ni++) {
            int n0 = bn + warp_n + ni * 8 + 2 * (l & 3);
            #pragma unroll
            for (int half = 0; half < 2; half++) {
                int m = m0 + half * 8;
                float v0 = acc[mi][ni][half * 2 + 0];
                float v1 = acc[mi][ni][half * 2 + 1];
                if (MODE == 1) {
                    float s0 = v0 / (1.f + expf(-v0));
                    float s1 = v1 / (1.f + expf(-v1));
                    if (bn < INNER)
                        *(uint32_t*)(g_u + (size_t)m * INNER + n0) = pack_half2(s0, s1);
                    else
                        *(uint32_t*)(g_z + (size_t)m * INNER + (n0 - INNER)) =
                            pack_half2(s0, s1);
                } else {
                    size_t o = (size_t)m * DD + n0;
                    float2 xv = *(const float2*)(extra + o);
                    *(float2*)(outp + o) = make_float2(xv.x + v0, xv.y + v1);
                }
            }
        }
    }
}

// ---------------- scan pass2: inline chunk-prefix + replay + gate ------------
__global__ __launch_bounds__(256) void scan_pass2()
{
    int b = blockIdx.z, c = blockIdx.y;
    int j = blockIdx.x * 256 + threadIdx.x;          // channel-pair 0..1023
    const int I2 = INNER / 2;
    // chunk-prefix state from per-chunk (P,q)
    float2 s = make_float2(0.f, 0.f);
    {
        size_t o = (size_t)b * NCHUNK * I2 + j;
        for (int cc = 0; cc < c; cc++) {
            float2 P = ((const float2*)g_P)[o];
            float2 q = ((const float2*)g_q)[o];
            s.x = fmaf(P.x, s.x, q.x);
            s.y = fmaf(P.y, s.y, q.y);
            o += I2;
        }
    }
    size_t idx = ((size_t)b * KK + (size_t)c * SCHUNK) * I2 + j;
    const __half2* lam2 = (const __half2*)g_lam;
    const __half2* u2   = (const __half2*)g_u;
    const __half2* z2   = (const __half2*)g_z;
    __half2* s2 = (__half2*)g_s;
    #pragma unroll 4
    for (int k = 0; k < SCHUNK; k++) {
        float2 lam = __half22float2(lam2[idx]);
        float2 u   = __half22float2(u2[idx]);
        float2 zz  = __half22float2(z2[idx]);
        s.x = fmaf(lam.x, s.x, (1.f - lam.x) * u.x);
        s.y = fmaf(lam.y, s.y, (1.f - lam.y) * u.y);
        s2[idx] = __floats2half2_rn(s.x * zz.x, s.y * zz.y);
        idx += I2;
    }
}

// ---------------- launch ------------------------------------------------------
extern "C" void kernel_launch(void* const* d_in, const int* in_sizes, int n_in,
                              void* d_out, int out_size)
{
    const float* x      = (const float*)d_in[0];
    const float* w_norm = (const float*)d_in[1];
    const float* W_in   = (const float*)d_in[2];
    const float* W_dt   = (const float*)d_in[3];
    const float* b_dt   = (const float*)d_in[4];
    const float* W_out  = (const float*)d_in[5];
    float* out = (float*)d_out;

    cudaFuncSetAttribute(gemm_tc<1>, cudaFuncAttributeMaxDynamicSharedMemorySize, GEMM_SMEM);
    cudaFuncSetAttribute(gemm_tc<2>, cudaFuncAttributeMaxDynamicSharedMemorySize, GEMM_SMEM);
    cudaFuncSetAttribute(gemm_tc<3>, cudaFuncAttributeMaxDynamicSharedMemorySize, GEMM_SMEM);

    convert_all<<<512, 256>>>(W_in, W_dt, W_out);
    rmsnorm_kernel<<<MROWS, 256>>>(x, w_norm);

    gemm_tc<1><<<dim3(2*INNER/128, MROWS/128), 256, GEMM_SMEM>>>(nullptr, nullptr);
    gemm_tc<2><<<dim3(INNER/128,   MROWS/128), 256, GEMM_SMEM>>>(b_dt, nullptr);

    scan_pass2<<<dim3(INNER/512, NCHUNK, BB), 256>>>();

    gemm_tc<3><<<dim3(DD/128,      MROWS/128), 256, GEMM_SMEM>>>(x, out);
}

// round 14
// speedup vs baseline: 1.2105x; 1.0185x over previous
#include <cuda_runtime.h>
#include <cuda_fp16.h>
#include <stdint.h>
#include <math.h>

#define BB 8
#define KK 2048
#define DD 1024
#define INNER 2048
#define MROWS (BB*KK)   // 16384
#define SCHUNK 64       // scan chunk length (half a GEMM tile M)
#define NCHUNK (KK/SCHUNK)  // 32

// ---------------- device scratch (no allocs allowed) ------------------------
__device__ __half g_h  [(size_t)MROWS*DD];      // RMSNorm out fp16      32 MB
__device__ __half g_u  [(size_t)MROWS*INNER];   // silu(u) fp16          64 MB
__device__ __half g_z  [(size_t)MROWS*INNER];   // silu(z) fp16          64 MB
__device__ __half g_lam[(size_t)MROWS*INNER];   // lambda fp16           64 MB
__device__ __half g_s  [(size_t)MROWS*INNER];   // scan*gate fp16        64 MB
__device__ __half g_wi [(size_t)2*INNER*DD];    // W_in fp16             16 MB
__device__ __half g_wd [(size_t)INNER*INNER];   // W_dt fp16              8 MB
__device__ __half g_wo [(size_t)DD*INNER];      // W_out fp16             4 MB
__device__ float  g_P  [(size_t)BB*NCHUNK*INNER];  // chunk decay prod    2 MB
__device__ float  g_q  [(size_t)BB*NCHUNK*INNER];  // chunk partial       2 MB

// ---------------- PTX helpers ------------------------------------------------
__device__ __forceinline__ uint32_t smem_u32(const void* p) {
    uint32_t a;
    asm("{ .reg .u64 t; cvta.to.shared.u64 t, %1; cvt.u32.u64 %0, t; }"
        : "=r"(a) : "l"(p));
    return a;
}
__device__ __forceinline__ void cp_async16(uint32_t dst, const void* src) {
    asm volatile("cp.async.cg.shared.global [%0], [%1], 16;\n"
                 :: "r"(dst), "l"(src) : "memory");
}
__device__ __forceinline__ void cp_commit() {
    asm volatile("cp.async.commit_group;\n" ::: "memory");
}
template <int N>
__device__ __forceinline__ void cp_wait() {
    asm volatile("cp.async.wait_group %0;\n" :: "n"(N) : "memory");
}
__device__ __forceinline__ void ldsm4(uint32_t* r, uint32_t addr) {
    asm volatile("ldmatrix.sync.aligned.m8n8.x4.shared.b16 {%0,%1,%2,%3}, [%4];"
                 : "=r"(r[0]), "=r"(r[1]), "=r"(r[2]), "=r"(r[3]) : "r"(addr));
}
__device__ __forceinline__ void mma16816(float* c, const uint32_t* a,
                                         uint32_t b0, uint32_t b1) {
    asm volatile("mma.sync.aligned.m16n8k16.row.col.f32.f16.f16.f32 "
                 "{%0,%1,%2,%3}, {%4,%5,%6,%7}, {%8,%9}, {%0,%1,%2,%3};"
                 : "+f"(c[0]), "+f"(c[1]), "+f"(c[2]), "+f"(c[3])
                 : "r"(a[0]), "r"(a[1]), "r"(a[2]), "r"(a[3]), "r"(b0), "r"(b1));
}
__device__ __forceinline__ uint32_t pack_half2(float a, float b) {
    __half2 h = __halves2half2(__float2half_rn(a), __float2half_rn(b));
    return *(uint32_t*)&h;
}

// ---------------- fused prep: rmsnorm rows + weight converts -----------------
// blocks [0, MROWS)          : rmsnorm of row blockIdx.x
// blocks [MROWS, MROWS+512)  : grid-stride convert of all three weights
__global__ __launch_bounds__(256) void prep_kernel(
    const float* __restrict__ x, const float* __restrict__ w,
    const float* __restrict__ wi, const float* __restrict__ wd,
    const float* __restrict__ wo)
{
    if (blockIdx.x < MROWS) {
        int row = blockIdx.x;
        const float4* xr = (const float4*)(x + (size_t)row * DD);
        float4 v = xr[threadIdx.x];
        float ss = v.x*v.x + v.y*v.y + v.z*v.z + v.w*v.w;
        #pragma unroll
        for (int o = 16; o > 0; o >>= 1) ss += __shfl_xor_sync(0xffffffffu, ss, o);
        __shared__ float red[8];
        if ((threadIdx.x & 31) == 0) red[threadIdx.x >> 5] = ss;
        __syncthreads();
        float tot = red[0]+red[1]+red[2]+red[3]+red[4]+red[5]+red[6]+red[7];
        float inv = rsqrtf(tot * (1.0f / DD) + 1e-5f);
        float4 wv = ((const float4*)w)[threadIdx.x];
        size_t base = (size_t)row * DD + threadIdx.x * 4;
        *(uint2*)(g_h + base) = make_uint2(
            pack_half2(v.x*inv*wv.x, v.y*inv*wv.y),
            pack_half2(v.z*inv*wv.z, v.w*inv*wv.w));
        return;
    }
    const size_t n0 = (size_t)2*INNER*DD >> 2;
    const size_t n1 = (size_t)INNER*INNER >> 2;
    const size_t n2 = (size_t)DD*INNER   >> 2;
    size_t stride = (size_t)512 * blockDim.x;
    size_t t0 = (size_t)(blockIdx.x - MROWS) * blockDim.x + threadIdx.x;
    for (size_t i = t0; i < n0; i += stride) {
        float4 v = ((const float4*)wi)[i];
        *(uint2*)(g_wi + 4*i) = make_uint2(pack_half2(v.x, v.y), pack_half2(v.z, v.w));
    }
    for (size_t i = t0; i < n1; i += stride) {
        float4 v = ((const float4*)wd)[i];
        *(uint2*)(g_wd + 4*i) = make_uint2(pack_half2(v.x, v.y), pack_half2(v.z, v.w));
    }
    for (size_t i = t0; i < n2; i += stride) {
        float4 v = ((const float4*)wo)[i];
        *(uint2*)(g_wo + 4*i) = make_uint2(pack_half2(v.x, v.y), pack_half2(v.z, v.w));
    }
}

// ---------------- mma.sync fp16 NT GEMM --------------------------------------
// C[M,N] = A[M,Kd]*B[N,Kd]^T, fp32 accumulate.
// MODE 1: A=g_h, B=g_wi : epi silu -> g_u (n<INNER) / g_z
// MODE 2: A=g_u, B=g_wd : epi lambda=sigmoid(v+b_dt) -> g_lam
//                         + FUSED 64-row chunk-scan pass1 -> g_P, g_q
// MODE 3: A=g_s, B=g_wo : epi x + v -> out
// BM=BN=128, BK=64; 8 warps 2(m)x4(n), warp tile 64x32; 3-stage cp.async.
#define ROWB  144
#define TEN_B (128*ROWB)        // 18432 per tensor per stage
#define NSTG  3
#define STG_B (2*TEN_B)         // 36864
#define GEMM_SMEM (NSTG*STG_B)  // 110592 -> 2 CTAs/SM
#define LAM_PITCH 130           // halves; pitch/2 odd -> conflict-light

template <int MODE>
__global__ __launch_bounds__(256, 2) void gemm_tc(
    const float* __restrict__ extra, float* __restrict__ outp)
{
    const __half *A, *B0;
    int Kd;
    if (MODE == 1)      { A = g_h; B0 = g_wi; Kd = DD;    }
    else if (MODE == 2) { A = g_u; B0 = g_wd; Kd = INNER; }
    else                { A = g_s; B0 = g_wo; Kd = INNER; }
    const int NT = Kd / 64;

    extern __shared__ __align__(128) char sm[];
    uint32_t sbase = smem_u32(sm);
    const int tid = threadIdx.x;
    const int l   = tid & 31;
    const int wid = tid >> 5;
    const int bm  = blockIdx.y * 128;
    const int bn  = blockIdx.x * 128;
    const int warp_m = (wid & 1) * 64;
    const int warp_n = (wid >> 1) * 32;

    const __half* srcA = A  + (size_t)bm * Kd;
    const __half* srcB = B0 + (size_t)bn * Kd;

    auto load_stage = [&](int stg, int kc) {
        uint32_t base = sbase + stg * STG_B;
        #pragma unroll
        for (int i = 0; i < 8; i++) {
            int c   = tid + i * 256;          // 0..2047
            int tns = c >> 10;                // 0: A, 1: B
            int idx = c & 1023;
            int row = idx >> 3;               // 0..127
            int seg = idx & 7;                // 16B segments of 128B row
            uint32_t dst = base + tns * TEN_B + row * ROWB + seg * 16;
            const __half* sp = tns ? srcB : srcA;
            cp_async16(dst, (const char*)(sp + (size_t)row * Kd + kc) + seg * 16);
        }
    };

    float acc[4][4][4];
    #pragma unroll
    for (int mi = 0; mi < 4; mi++)
        #pragma unroll
        for (int ni = 0; ni < 4; ni++)
            #pragma unroll
            for (int c = 0; c < 4; c++) acc[mi][ni][c] = 0.0f;

    const uint32_t a_off = (warp_m + (l & 15)) * ROWB + 16 * (l >> 4);
    const uint32_t b_off = TEN_B + (warp_n + (l & 15)) * ROWB + 16 * (l >> 4);

    load_stage(0, 0);  cp_commit();
    load_stage(1, 64); cp_commit();

    uint32_t bh[2][2][4];   // [buf][g][frag] — B frags double-buffered over k16

    for (int t = 0; t < NT; t++) {
        if (t + 1 < NT) cp_wait<1>();
        else            cp_wait<0>();
        __syncthreads();
        if (t + 2 < NT) { load_stage((t + 2) % 3, (t + 2) * 64); cp_commit(); }

        uint32_t sb = sbase + (t % 3) * STG_B;

        #pragma unroll
        for (int g = 0; g < 2; g++)
            ldsm4(bh[0][g], sb + b_off + g * (16*ROWB));

        #pragma unroll
        for (int k16 = 0; k16 < 4; k16++) {
            const int cur = k16 & 1, nxt = cur ^ 1;
            const uint32_t koff = k16 * 32;
            if (k16 < 3) {
                #pragma unroll
                for (int g = 0; g < 2; g++)
                    ldsm4(bh[nxt][g], sb + b_off + g * (16*ROWB) + koff + 32);
            }
            #pragma unroll
            for (int mh = 0; mh < 2; mh++) {
                uint32_t ah[2][4];
                ldsm4(ah[0], sb + a_off + (mh*2+0) * (16*ROWB) + koff);
                ldsm4(ah[1], sb + a_off + (mh*2+1) * (16*ROWB) + koff);
                #pragma unroll
                for (int mi2 = 0; mi2 < 2; mi2++) {
                    const int mi = mh * 2 + mi2;
                    #pragma unroll
                    for (int ni = 0; ni < 4; ni++) {
                        const int g = ni >> 1, s = ni & 1;
                        mma16816(acc[mi][ni], ah[mi2],
                                 bh[cur][g][s], bh[cur][g][s + 2]);
                    }
                }
            }
        }
    }

    // ---------------- epilogue ----------------------------------------------
    if (MODE == 2) {
        // lambda -> g_lam + stage-smem; then fused 64-row chunk pass1
        __syncthreads();                     // all stage-smem reads done
        __half* lam_sm = (__half*)sm;
        #pragma unroll
        for (int mi = 0; mi < 4; mi++) {
            int mloc0 = warp_m + mi * 16 + (l >> 2);
            #pragma unroll
            for (int ni = 0; ni < 4; ni++) {
                int nloc = warp_n + ni * 8 + 2 * (l & 3);
                float2 bv = *(const float2*)(extra + bn + nloc);
                #pragma unroll
                for (int half = 0; half < 2; half++) {
                    int mloc = mloc0 + half * 8;
                    float l0 = 1.f / (1.f + expf(-(acc[mi][ni][half*2+0] + bv.x)));
                    float l1 = 1.f / (1.f + expf(-(acc[mi][ni][half*2+1] + bv.y)));
                    uint32_t p = pack_half2(l0, l1);
                    *(uint32_t*)(g_lam + (size_t)(bm + mloc) * INNER + bn + nloc) = p;
                    *(uint32_t*)(lam_sm + mloc * LAM_PITCH + nloc) = p;
                }
            }
        }
        __syncthreads();
        // per-channel 64-row recurrence: thread -> (half hh, channel j)
        int j  = tid & 127;
        int hh = tid >> 7;
        const __half* urow = g_u + (size_t)(bm + hh * 64) * INNER + bn + j;
        float P = 1.f, q = 0.f;
        #pragma unroll 8
        for (int r = 0; r < 64; r++) {
            float lam = __half2float(lam_sm[(hh * 64 + r) * LAM_PITCH + j]);
            float uu  = __half2float(urow[(size_t)r * INNER]);
            q = fmaf(lam, q, (1.f - lam) * uu);
            P *= lam;
        }
        // direct store at 64-row chunk granularity (no combine needed)
        int b  = bm >> 11;                       // / KK
        int c2 = ((bm & (KK - 1)) >> 6) + hh;    // 64-row chunk index 0..31
        size_t o = ((size_t)b * NCHUNK + c2) * INNER + bn + j;
        g_P[o] = P;
        g_q[o] = q;
        return;
    }

    #pragma unroll
    for (int mi = 0; mi < 4; mi++) {
        int m0 = bm + warp_m + mi * 16 + (l >> 2);
        #pragma unroll
        for (int ni = 0; ni < 4; ni++) {
            int n0 = bn + warp_n + ni * 8 + 2 * (l & 3);
            #pragma unroll
            for (int half = 0; half < 2; half++) {
                int m = m0 + half * 8;
                float v0 = acc[mi][ni][half * 2 + 0];
                float v1 = acc[mi][ni][half * 2 + 1];
                if (MODE == 1) {
                    float s0 = v0 / (1.f + expf(-v0));
                    float s1 = v1 / (1.f + expf(-v1));
                    if (bn < INNER)
                        *(uint32_t*)(g_u + (size_t)m * INNER + n0) = pack_half2(s0, s1);
                    else
                        *(uint32_t*)(g_z + (size_t)m * INNER + (n0 - INNER)) =
                            pack_half2(s0, s1);
                } else {
                    size_t o = (size_t)m * DD + n0;
                    float2 xv = *(const float2*)(extra + o);
                    *(float2*)(outp + o) = make_float2(xv.x + v0, xv.y + v1);
                }
            }
        }
    }
}

// ---------------- scan pass2: inline chunk-prefix + replay + gate ------------
__global__ __launch_bounds__(256) void scan_pass2()
{
    int b = blockIdx.z, c = blockIdx.y;              // c: 64-row chunk 0..31
    int j = blockIdx.x * 256 + threadIdx.x;          // channel-pair 0..1023
    const int I2 = INNER / 2;
    // chunk-prefix state from per-chunk (P,q)
    float2 s = make_float2(0.f, 0.f);
    {
        size_t o = (size_t)b * NCHUNK * I2 + j;
        for (int cc = 0; cc < c; cc++) {
            float2 P = ((const float2*)g_P)[o];
            float2 q = ((const float2*)g_q)[o];
            s.x = fmaf(P.x, s.x, q.x);
            s.y = fmaf(P.y, s.y, q.y);
            o += I2;
        }
    }
    size_t idx = ((size_t)b * KK + (size_t)c * SCHUNK) * I2 + j;
    const __half2* lam2 = (const __half2*)g_lam;
    const __half2* u2   = (const __half2*)g_u;
    const __half2* z2   = (const __half2*)g_z;
    __half2* s2 = (__half2*)g_s;
    #pragma unroll 4
    for (int k = 0; k < SCHUNK; k++) {
        float2 lam = __half22float2(lam2[idx]);
        float2 u   = __half22float2(u2[idx]);
        float2 zz  = __half22float2(z2[idx]);
        s.x = fmaf(lam.x, s.x, (1.f - lam.x) * u.x);
        s.y = fmaf(lam.y, s.y, (1.f - lam.y) * u.y);
        s2[idx] = __floats2half2_rn(s.x * zz.x, s.y * zz.y);
        idx += I2;
    }
}

// ---------------- launch ------------------------------------------------------
extern "C" void kernel_launch(void* const* d_in, const int* in_sizes, int n_in,
                              void* d_out, int out_size)
{
    const float* x      = (const float*)d_in[0];
    const float* w_norm = (const float*)d_in[1];
    const float* W_in   = (const float*)d_in[2];
    const float* W_dt   = (const float*)d_in[3];
    const float* b_dt   = (const float*)d_in[4];
    const float* W_out  = (const float*)d_in[5];
    float* out = (float*)d_out;

    cudaFuncSetAttribute(gemm_tc<1>, cudaFuncAttributeMaxDynamicSharedMemorySize, GEMM_SMEM);
    cudaFuncSetAttribute(gemm_tc<2>, cudaFuncAttributeMaxDynamicSharedMemorySize, GEMM_SMEM);
    cudaFuncSetAttribute(gemm_tc<3>, cudaFuncAttributeMaxDynamicSharedMemorySize, GEMM_SMEM);

    prep_kernel<<<MROWS + 512, 256>>>(x, w_norm, W_in, W_dt, W_out);

    gemm_tc<1><<<dim3(2*INNER/128, MROWS/128), 256, GEMM_SMEM>>>(nullptr, nullptr);
    gemm_tc<2><<<dim3(INNER/128,   MROWS/128), 256, GEMM_SMEM>>>(b_dt, nullptr);

    scan_pass2<<<dim3(INNER/512, NCHUNK, BB), 256>>>();

    gemm_tc<3><<<dim3(DD/128,      MROWS/128), 256, GEMM_SMEM>>>(x, out);
}

// round 15
// speedup vs baseline: 1.2124x; 1.0016x over previous
#include <cuda_runtime.h>
#include <cuda_fp16.h>
#include <stdint.h>
#include <math.h>

#define BB 8
#define KK 2048
#define DD 1024
#define INNER 2048
#define MROWS (BB*KK)   // 16384
#define SCHUNK 64       // scan chunk length (half a GEMM tile M)
#define NCHUNK (KK/SCHUNK)  // 32

// ---------------- device scratch (no allocs allowed) ------------------------
__device__ __half g_h  [(size_t)MROWS*DD];      // RMSNorm out fp16      32 MB
__device__ __half g_u  [(size_t)MROWS*INNER];   // silu(u) fp16          64 MB
__device__ __half g_z  [(size_t)MROWS*INNER];   // silu(z) fp16          64 MB
__device__ __half g_lam[(size_t)MROWS*INNER];   // lambda fp16           64 MB
__device__ __half g_s  [(size_t)MROWS*INNER];   // scan*gate fp16        64 MB
__device__ __half g_wi [(size_t)2*INNER*DD];    // W_in fp16             16 MB
__device__ __half g_wd [(size_t)INNER*INNER];   // W_dt fp16              8 MB
__device__ __half g_wo [(size_t)DD*INNER];      // W_out fp16             4 MB
__device__ float  g_P  [(size_t)BB*NCHUNK*INNER];  // chunk decay prod    2 MB
__device__ float  g_q  [(size_t)BB*NCHUNK*INNER];  // chunk partial       2 MB

// ---------------- PTX helpers ------------------------------------------------
__device__ __forceinline__ uint32_t smem_u32(const void* p) {
    uint32_t a;
    asm("{ .reg .u64 t; cvta.to.shared.u64 t, %1; cvt.u32.u64 %0, t; }"
        : "=r"(a) : "l"(p));
    return a;
}
__device__ __forceinline__ void cp_async16(uint32_t dst, const void* src) {
    asm volatile("cp.async.cg.shared.global [%0], [%1], 16;\n"
                 :: "r"(dst), "l"(src) : "memory");
}
__device__ __forceinline__ void cp_commit() {
    asm volatile("cp.async.commit_group;\n" ::: "memory");
}
template <int N>
__device__ __forceinline__ void cp_wait() {
    asm volatile("cp.async.wait_group %0;\n" :: "n"(N) : "memory");
}
__device__ __forceinline__ void ldsm4(uint32_t* r, uint32_t addr) {
    asm volatile("ldmatrix.sync.aligned.m8n8.x4.shared.b16 {%0,%1,%2,%3}, [%4];"
                 : "=r"(r[0]), "=r"(r[1]), "=r"(r[2]), "=r"(r[3]) : "r"(addr));
}
__device__ __forceinline__ void mma16816(float* c, const uint32_t* a,
                                         uint32_t b0, uint32_t b1) {
    asm volatile("mma.sync.aligned.m16n8k16.row.col.f32.f16.f16.f32 "
                 "{%0,%1,%2,%3}, {%4,%5,%6,%7}, {%8,%9}, {%0,%1,%2,%3};"
                 : "+f"(c[0]), "+f"(c[1]), "+f"(c[2]), "+f"(c[3])
                 : "r"(a[0]), "r"(a[1]), "r"(a[2]), "r"(a[3]), "r"(b0), "r"(b1));
}
__device__ __forceinline__ uint32_t pack_half2(float a, float b) {
    __half2 h = __halves2half2(__float2half_rn(a), __float2half_rn(b));
    return *(uint32_t*)&h;
}

// ---------------- fused prep: rmsnorm rows + weight converts -----------------
__global__ __launch_bounds__(256) void prep_kernel(
    const float* __restrict__ x, const float* __restrict__ w,
    const float* __restrict__ wi, const float* __restrict__ wd,
    const float* __restrict__ wo)
{
    if (blockIdx.x < MROWS) {
        int row = blockIdx.x;
        const float4* xr = (const float4*)(x + (size_t)row * DD);
        float4 v = xr[threadIdx.x];
        float ss = v.x*v.x + v.y*v.y + v.z*v.z + v.w*v.w;
        #pragma unroll
        for (int o = 16; o > 0; o >>= 1) ss += __shfl_xor_sync(0xffffffffu, ss, o);
        __shared__ float red[8];
        if ((threadIdx.x & 31) == 0) red[threadIdx.x >> 5] = ss;
        __syncthreads();
        float tot = red[0]+red[1]+red[2]+red[3]+red[4]+red[5]+red[6]+red[7];
        float inv = rsqrtf(tot * (1.0f / DD) + 1e-5f);
        float4 wv = ((const float4*)w)[threadIdx.x];
        size_t base = (size_t)row * DD + threadIdx.x * 4;
        *(uint2*)(g_h + base) = make_uint2(
            pack_half2(v.x*inv*wv.x, v.y*inv*wv.y),
            pack_half2(v.z*inv*wv.z, v.w*inv*wv.w));
        return;
    }
    const size_t n0 = (size_t)2*INNER*DD >> 2;
    const size_t n1 = (size_t)INNER*INNER >> 2;
    const size_t n2 = (size_t)DD*INNER   >> 2;
    size_t stride = (size_t)512 * blockDim.x;
    size_t t0 = (size_t)(blockIdx.x - MROWS) * blockDim.x + threadIdx.x;
    for (size_t i = t0; i < n0; i += stride) {
        float4 v = ((const float4*)wi)[i];
        *(uint2*)(g_wi + 4*i) = make_uint2(pack_half2(v.x, v.y), pack_half2(v.z, v.w));
    }
    for (size_t i = t0; i < n1; i += stride) {
        float4 v = ((const float4*)wd)[i];
        *(uint2*)(g_wd + 4*i) = make_uint2(pack_half2(v.x, v.y), pack_half2(v.z, v.w));
    }
    for (size_t i = t0; i < n2; i += stride) {
        float4 v = ((const float4*)wo)[i];
        *(uint2*)(g_wo + 4*i) = make_uint2(pack_half2(v.x, v.y), pack_half2(v.z, v.w));
    }
}

// ---------------- mma.sync fp16 NT GEMM --------------------------------------
// C[M,N] = A[M,Kd]*B[N,Kd]^T, fp32 accumulate.
// MODE 1: A=g_h, B=g_wi : epi silu -> g_u (n<INNER) / g_z
// MODE 2: A=g_u, B=g_wd : epi lambda=sigmoid(v+b_dt) -> g_lam
//                         + FUSED 64-row chunk-scan pass1 -> g_P, g_q
// MODE 3: A=g_s, B=g_wo : epi x + v -> out
// BM=BN=128, BK=64; 8 warps 2(m)x4(n), warp tile 64x32; 3-stage cp.async.
#define ROWB  144
#define TEN_B (128*ROWB)        // 18432 per tensor per stage
#define NSTG  3
#define STG_B (2*TEN_B)         // 36864
#define GEMM_SMEM (NSTG*STG_B)  // 110592 -> 2 CTAs/SM
#define LAM_PITCH 130           // halves; pitch/2 odd -> conflict-light

template <int MODE>
__global__ __launch_bounds__(256, 2) void gemm_tc(
    const float* __restrict__ extra, float* __restrict__ outp)
{
    const __half *A, *B0;
    int Kd;
    if (MODE == 1)      { A = g_h; B0 = g_wi; Kd = DD;    }
    else if (MODE == 2) { A = g_u; B0 = g_wd; Kd = INNER; }
    else                { A = g_s; B0 = g_wo; Kd = INNER; }
    const int NT = Kd / 64;

    extern __shared__ __align__(128) char sm[];
    uint32_t sbase = smem_u32(sm);
    const int tid = threadIdx.x;
    const int l   = tid & 31;
    const int wid = tid >> 5;
    const int bm  = blockIdx.y * 128;
    const int bn  = blockIdx.x * 128;
    const int warp_m = (wid & 1) * 64;
    const int warp_n = (wid >> 1) * 32;

    const __half* srcA = A  + (size_t)bm * Kd;
    const __half* srcB = B0 + (size_t)bn * Kd;

    auto load_stage = [&](int stg, int kc) {
        uint32_t base = sbase + stg * STG_B;
        #pragma unroll
        for (int i = 0; i < 8; i++) {
            int c   = tid + i * 256;          // 0..2047
            int tns = c >> 10;                // 0: A, 1: B
            int idx = c & 1023;
            int row = idx >> 3;               // 0..127
            int seg = idx & 7;                // 16B segments of 128B row
            uint32_t dst = base + tns * TEN_B + row * ROWB + seg * 16;
            const __half* sp = tns ? srcB : srcA;
            cp_async16(dst, (const char*)(sp + (size_t)row * Kd + kc) + seg * 16);
        }
    };

    float acc[4][4][4];
    #pragma unroll
    for (int mi = 0; mi < 4; mi++)
        #pragma unroll
        for (int ni = 0; ni < 4; ni++)
            #pragma unroll
            for (int c = 0; c < 4; c++) acc[mi][ni][c] = 0.0f;

    const uint32_t a_off = (warp_m + (l & 15)) * ROWB + 16 * (l >> 4);
    const uint32_t b_off = TEN_B + (warp_n + (l & 15)) * ROWB + 16 * (l >> 4);

    load_stage(0, 0);  cp_commit();
    load_stage(1, 64); cp_commit();

    uint32_t bh[2][2][4];   // [buf][g][frag] — B frags double-buffered over k16

    for (int t = 0; t < NT; t++) {
        if (t + 1 < NT) cp_wait<1>();
        else            cp_wait<0>();
        __syncthreads();
        if (t + 2 < NT) { load_stage((t + 2) % 3, (t + 2) * 64); cp_commit(); }

        uint32_t sb = sbase + (t % 3) * STG_B;

        #pragma unroll
        for (int g = 0; g < 2; g++)
            ldsm4(bh[0][g], sb + b_off + g * (16*ROWB));

        #pragma unroll
        for (int k16 = 0; k16 < 4; k16++) {
            const int cur = k16 & 1, nxt = cur ^ 1;
            const uint32_t koff = k16 * 32;
            if (k16 < 3) {
                #pragma unroll
                for (int g = 0; g < 2; g++)
                    ldsm4(bh[nxt][g], sb + b_off + g * (16*ROWB) + koff + 32);
            }
            #pragma unroll
            for (int mh = 0; mh < 2; mh++) {
                uint32_t ah[2][4];
                ldsm4(ah[0], sb + a_off + (mh*2+0) * (16*ROWB) + koff);
                ldsm4(ah[1], sb + a_off + (mh*2+1) * (16*ROWB) + koff);
                #pragma unroll
                for (int mi2 = 0; mi2 < 2; mi2++) {
                    const int mi = mh * 2 + mi2;
                    #pragma unroll
                    for (int ni = 0; ni < 4; ni++) {
                        const int g = ni >> 1, s = ni & 1;
                        mma16816(acc[mi][ni], ah[mi2],
                                 bh[cur][g][s], bh[cur][g][s + 2]);
                    }
                }
            }
        }
    }

    // ---------------- epilogue ----------------------------------------------
    if (MODE == 2) {
        // lambda -> g_lam + stage-smem; then fused 64-row chunk pass1
        __syncthreads();                     // all stage-smem reads done
        __half* lam_sm = (__half*)sm;
        #pragma unroll
        for (int mi = 0; mi < 4; mi++) {
            int mloc0 = warp_m + mi * 16 + (l >> 2);
            #pragma unroll
            for (int ni = 0; ni < 4; ni++) {
                int nloc = warp_n + ni * 8 + 2 * (l & 3);
                float2 bv = *(const float2*)(extra + bn + nloc);
                #pragma unroll
                for (int half = 0; half < 2; half++) {
                    int mloc = mloc0 + half * 8;
                    float l0 = 1.f / (1.f + expf(-(acc[mi][ni][half*2+0] + bv.x)));
                    float l1 = 1.f / (1.f + expf(-(acc[mi][ni][half*2+1] + bv.y)));
                    uint32_t p = pack_half2(l0, l1);
                    *(uint32_t*)(g_lam + (size_t)(bm + mloc) * INNER + bn + nloc) = p;
                    *(uint32_t*)(lam_sm + mloc * LAM_PITCH + nloc) = p;
                }
            }
        }
        __syncthreads();
        // per-channel 64-row recurrence: thread -> (half hh, channel j)
        int j  = tid & 127;
        int hh = tid >> 7;
        const __half* urow = g_u + (size_t)(bm + hh * 64) * INNER + bn + j;
        float P = 1.f, q = 0.f;
        #pragma unroll 8
        for (int r = 0; r < 64; r++) {
            float lam = __half2float(lam_sm[(hh * 64 + r) * LAM_PITCH + j]);
            float uu  = __half2float(urow[(size_t)r * INNER]);
            q = fmaf(lam, q, (1.f - lam) * uu);
            P *= lam;
        }
        // direct store at 64-row chunk granularity (no combine needed)
        int b  = bm >> 11;                       // / KK
        int c2 = ((bm & (KK - 1)) >> 6) + hh;    // 64-row chunk index 0..31
        size_t o = ((size_t)b * NCHUNK + c2) * INNER + bn + j;
        g_P[o] = P;
        g_q[o] = q;
        return;
    }

    #pragma unroll
    for (int mi = 0; mi < 4; mi++) {
        int m0 = bm + warp_m + mi * 16 + (l >> 2);
        #pragma unroll
        for (int ni = 0; ni < 4; ni++) {
            int n0 = bn + warp_n + ni * 8 + 2 * (l & 3);
            #pragma unroll
            for (int half = 0; half < 2; half++) {
                int m = m0 + half * 8;
                float v0 = acc[mi][ni][half * 2 + 0];
                float v1 = acc[mi][ni][half * 2 + 1];
                if (MODE == 1) {
                    float s0 = v0 / (1.f + expf(-v0));
                    float s1 = v1 / (1.f + expf(-v1));
                    if (bn < INNER)
                        *(uint32_t*)(g_u + (size_t)m * INNER + n0) = pack_half2(s0, s1);
                    else
                        *(uint32_t*)(g_z + (size_t)m * INNER + (n0 - INNER)) =
                            pack_half2(s0, s1);
                } else {
                    size_t o = (size_t)m * DD + n0;
                    float2 xv = *(const float2*)(extra + o);
                    *(float2*)(outp + o) = make_float2(xv.x + v0, xv.y + v1);
                }
            }
        }
    }
}

// ---------------- scan pass2: 4 channels/thread + one-ahead prefetch ---------
__global__ __launch_bounds__(256) void scan_pass2()
{
    int b = blockIdx.z, c = blockIdx.y;              // c: 64-row chunk 0..31
    int j = blockIdx.x * 256 + threadIdx.x;          // channel-quad 0..511
    const int I4 = INNER / 4;                        // uint2/float4 row stride
    // chunk-prefix state from per-chunk (P,q), 4 channels
    float4 s = make_float4(0.f, 0.f, 0.f, 0.f);
    {
        size_t o = (size_t)b * NCHUNK * I4 + j;
        for (int cc = 0; cc < c; cc++) {
            float4 P = ((const float4*)g_P)[o];
            float4 q = ((const float4*)g_q)[o];
            s.x = fmaf(P.x, s.x, q.x);
            s.y = fmaf(P.y, s.y, q.y);
            s.z = fmaf(P.z, s.z, q.z);
            s.w = fmaf(P.w, s.w, q.w);
            o += I4;
        }
    }
    size_t idx = ((size_t)b * KK + (size_t)c * SCHUNK) * I4 + j;
    const uint2* lam4 = (const uint2*)g_lam;
    const uint2* u4   = (const uint2*)g_u;
    const uint2* z4   = (const uint2*)g_z;
    uint2* s4 = (uint2*)g_s;
    // one-ahead register prefetch (loads independent of the recurrence)
    uint2 lamN = lam4[idx], uN = u4[idx], zN = z4[idx];
    #pragma unroll 4
    for (int k = 0; k < SCHUNK; k++) {
        uint2 lamc = lamN, uc = uN, zc = zN;
        if (k + 1 < SCHUNK) {
            lamN = lam4[idx + I4];
            uN   = u4[idx + I4];
            zN   = z4[idx + I4];
        }
        float2 la = __half22float2(*(const __half2*)&lamc.x);
        float2 lb = __half22float2(*(const __half2*)&lamc.y);
        float2 ua = __half22float2(*(const __half2*)&uc.x);
        float2 ub = __half22float2(*(const __half2*)&uc.y);
        float2 za = __half22float2(*(const __half2*)&zc.x);
        float2 zb = __half22float2(*(const __half2*)&zc.y);
        s.x = fmaf(la.x, s.x, (1.f - la.x) * ua.x);
        s.y = fmaf(la.y, s.y, (1.f - la.y) * ua.y);
        s.z = fmaf(lb.x, s.z, (1.f - lb.x) * ub.x);
        s.w = fmaf(lb.y, s.w, (1.f - lb.y) * ub.y);
        uint2 outv;
        outv.x = pack_half2(s.x * za.x, s.y * za.y);
        outv.y = pack_half2(s.z * zb.x, s.w * zb.y);
        s4[idx] = outv;
        idx += I4;
    }
}

// ---------------- launch ------------------------------------------------------
extern "C" void kernel_launch(void* const* d_in, const int* in_sizes, int n_in,
                              void* d_out, int out_size)
{
    const float* x      = (const float*)d_in[0];
    const float* w_norm = (const float*)d_in[1];
    const float* W_in   = (const float*)d_in[2];
    const float* W_dt   = (const float*)d_in[3];
    const float* b_dt   = (const float*)d_in[4];
    const float* W_out  = (const float*)d_in[5];
    float* out = (float*)d_out;

    cudaFuncSetAttribute(gemm_tc<1>, cudaFuncAttributeMaxDynamicSharedMemorySize, GEMM_SMEM);
    cudaFuncSetAttribute(gemm_tc<2>, cudaFuncAttributeMaxDynamicSharedMemorySize, GEMM_SMEM);
    cudaFuncSetAttribute(gemm_tc<3>, cudaFuncAttributeMaxDynamicSharedMemorySize, GEMM_SMEM);

    prep_kernel<<<MROWS + 512, 256>>>(x, w_norm, W_in, W_dt, W_out);

    gemm_tc<1><<<dim3(2*INNER/128, MROWS/128), 256, GEMM_SMEM>>>(nullptr, nullptr);
    gemm_tc<2><<<dim3(INNER/128,   MROWS/128), 256, GEMM_SMEM>>>(b_dt, nullptr);

    scan_pass2<<<dim3(INNER/1024, NCHUNK, BB), 256>>>();

    gemm_tc<3><<<dim3(DD/128,      MROWS/128), 256, GEMM_SMEM>>>(x, out);
}